// round 10
// baseline (speedup 1.0000x reference)
#include <cuda_runtime.h>
#include <cuda_fp16.h>
#include <math.h>

#define EMB   128
#define NSP   95
#define NPAIR (NSP * NSP)
#define NRBF  16
#define EPW   4
#define EMAX  300000

// ---------------- device-global scratch ----------------
__device__ float g_Wc[NRBF * EMB];
__device__ float g_bias[EMB];
__device__ float g_T1[NSP * EMB];
__device__ float g_T2[NSP * EMB];
__device__ float g_Vs1[NSP * 6 * EMB];
__device__ float g_Vs2[NSP * 6 * EMB];
__device__ float g_C[3 * EMB];
__device__ float g_S1[NSP * 3];
__device__ float g_S2[NSP * 3];
__device__ float g_sb;
// pair-combined tables
__device__ __half g_Vc[NPAIR * 6 * EMB];   // 13.9 MB fp16
__device__ float  g_Tc[NPAIR * EMB];       // 4.6 MB fp32 (bias folded in)
// edge binning
__device__ int g_cnt[NPAIR];
__device__ int g_cur[NPAIR];
__device__ int g_off[NPAIR + 1];
__device__ int g_perm[EMAX];

// ---------------- precompute 1: scalar tables (slim) ----------------
__global__ void pre_tables(const float* __restrict__ W_rbf,
                           const float* __restrict__ b_rbf,
                           const float* __restrict__ W_scalar,
                           const float* __restrict__ b_scalar,
                           const float* __restrict__ emb,
                           const float* __restrict__ b_vector,
                           const float* __restrict__ W_v2s) {
    __shared__ float sh[128];
    int m = threadIdx.x;
    int b = blockIdx.x;
    if (b < NRBF) {
        float s = 0.f;
        #pragma unroll 4
        for (int c = 0; c < EMB; c++)
            s = fmaf(W_rbf[b * EMB + c], W_scalar[(2 * EMB + c) * EMB + m], s);
        g_Wc[b * EMB + m] = s;
    } else if (b == NRBF) {
        float s = b_scalar[m];
        #pragma unroll 4
        for (int c = 0; c < EMB; c++)
            s = fmaf(b_rbf[c], W_scalar[(2 * EMB + c) * EMB + m], s);
        g_bias[m] = s;
    } else if (b < NRBF + 1 + NSP) {
        int z = b - NRBF - 1;
        float s1 = 0.f, s2 = 0.f;
        #pragma unroll 4
        for (int k = 0; k < EMB; k++) {
            float e = emb[z * EMB + k];
            s1 = fmaf(e, W_scalar[k * EMB + m], s1);
            s2 = fmaf(e, W_scalar[(EMB + k) * EMB + m], s2);
        }
        g_T1[z * EMB + m] = s1;
        g_T2[z * EMB + m] = s2;
    } else {
        int dp = b - (NRBF + 1 + NSP); // 0..2
        float s = 0.f;
        #pragma unroll 4
        for (int k = 0; k < EMB; k++)
            s = fmaf(b_vector[k], W_v2s[(k * 3 + dp) * EMB + m], s);
        g_C[dp * EMB + m] = s;
        if (dp == 0) {
            sh[m] = b_vector[m]; __syncthreads();
            for (int s2 = 64; s2 > 0; s2 >>= 1) { if (m < s2) sh[m] += sh[m + s2]; __syncthreads(); }
            if (m == 0) g_sb = sh[0];
        }
    }
}

// ---------------- precompute 2: U (smem) + S + Vs, one block per species ----------------
__global__ void pre_UVS(const float* __restrict__ vemb,
                        const float* __restrict__ W_vector,
                        const float* __restrict__ W_v2s) {
    __shared__ float s_ve[EMB * 3];
    __shared__ float s_U1[3][EMB];
    __shared__ float s_U2[3][EMB];
    int z = blockIdx.x;
    int t = threadIdx.x;   // 0..127

    #pragma unroll
    for (int d = 0; d < 3; d++)
        s_ve[t * 3 + d] = vemb[((size_t)z * EMB + t) * 3 + d];
    __syncthreads();

    // U[d,t] = sum_k' vemb[z,k',d] * W_vector[k',t]  (both halves)
    float u1[3] = {0.f, 0.f, 0.f}, u2[3] = {0.f, 0.f, 0.f};
    #pragma unroll 4
    for (int kp = 0; kp < EMB; kp++) {
        float w1 = W_vector[kp * EMB + t];
        float w2 = W_vector[(EMB + kp) * EMB + t];
        #pragma unroll
        for (int d = 0; d < 3; d++) {
            float v = s_ve[kp * 3 + d];
            u1[d] = fmaf(v, w1, u1[d]);
            u2[d] = fmaf(v, w2, u2[d]);
        }
    }
    #pragma unroll
    for (int d = 0; d < 3; d++) { s_U1[d][t] = u1[d]; s_U2[d][t] = u2[d]; }
    __syncthreads();

    // S sums (warp 0)
    if (t < 32) {
        #pragma unroll
        for (int d = 0; d < 3; d++) {
            float s1 = s_U1[d][t] + s_U1[d][t + 32] + s_U1[d][t + 64] + s_U1[d][t + 96];
            float s2 = s_U2[d][t] + s_U2[d][t + 32] + s_U2[d][t + 64] + s_U2[d][t + 96];
            #pragma unroll
            for (int o = 16; o > 0; o >>= 1) {
                s1 += __shfl_down_sync(0xffffffffu, s1, o);
                s2 += __shfl_down_sync(0xffffffffu, s2, o);
            }
            if (t == 0) { g_S1[z * 3 + d] = s1; g_S2[z * 3 + d] = s2; }
        }
    }

    // Vs[p,t] = sum_k U[d_p,k] * W_v2s[(k,dp_p),t]  (+ symmetric term for d!=dp)
    float a1[6] = {0.f,0.f,0.f,0.f,0.f,0.f};
    float a2[6] = {0.f,0.f,0.f,0.f,0.f,0.f};
    #pragma unroll 2
    for (int k = 0; k < EMB; k++) {
        float w0 = W_v2s[(k * 3 + 0) * EMB + t];
        float w1 = W_v2s[(k * 3 + 1) * EMB + t];
        float w2 = W_v2s[(k * 3 + 2) * EMB + t];
        float u10 = s_U1[0][k], u11 = s_U1[1][k], u12 = s_U1[2][k];
        float u20 = s_U2[0][k], u21 = s_U2[1][k], u22 = s_U2[2][k];
        a1[0] = fmaf(u10, w0, a1[0]);  a2[0] = fmaf(u20, w0, a2[0]);
        a1[1] = fmaf(u11, w1, a1[1]);  a2[1] = fmaf(u21, w1, a2[1]);
        a1[2] = fmaf(u12, w2, a1[2]);  a2[2] = fmaf(u22, w2, a2[2]);
        a1[3] = fmaf(u10, w1, fmaf(u11, w0, a1[3]));
        a2[3] = fmaf(u20, w1, fmaf(u21, w0, a2[3]));
        a1[4] = fmaf(u10, w2, fmaf(u12, w0, a1[4]));
        a2[4] = fmaf(u20, w2, fmaf(u22, w0, a2[4]));
        a1[5] = fmaf(u11, w2, fmaf(u12, w1, a1[5]));
        a2[5] = fmaf(u21, w2, fmaf(u22, w1, a2[5]));
    }
    #pragma unroll
    for (int p = 0; p < 6; p++) {
        g_Vs1[(z * 6 + p) * EMB + t] = a1[p];
        g_Vs2[(z * 6 + p) * EMB + t] = a2[p];
    }
}

// ---------------- precompute 3: pair-combined tables ----------------
__global__ void pre_pair(void) {
    int m = threadIdx.x;
    int pair = blockIdx.x;
    int zi = pair / NSP, zj = pair % NSP;
    g_Tc[pair * EMB + m] = g_T1[zi * EMB + m] + g_T2[zj * EMB + m] + g_bias[m];
    #pragma unroll
    for (int p = 0; p < 6; p++) {
        float v = g_Vs1[(zi * 6 + p) * EMB + m] + g_Vs2[(zj * 6 + p) * EMB + m];
        g_Vc[(pair * 6 + p) * EMB + m] = __float2half(v);
    }
}

// ---------------- binning kernels ----------------
__global__ void zero_k() {
    int i = blockIdx.x * 256 + threadIdx.x;
    if (i < NPAIR) { g_cnt[i] = 0; g_cur[i] = 0; }
}

__global__ void hist_k(const int* __restrict__ idnb_i, const int* __restrict__ idnb_j,
                       const int* __restrict__ Z, int E) {
    int e = blockIdx.x * 256 + threadIdx.x;
    if (e < E) {
        int pr = Z[idnb_i[e]] * NSP + Z[idnb_j[e]];
        atomicAdd(&g_cnt[pr], 1);
    }
}

__global__ void scan_k() {
    __shared__ int sh[1024];
    int t = threadIdx.x;
    const int IPT = (NPAIR + 1023) / 1024;  // 9
    int loc[IPT];
    int sum = 0;
    #pragma unroll
    for (int i = 0; i < IPT; i++) {
        int idx = t * IPT + i;
        int v = (idx < NPAIR) ? g_cnt[idx] : 0;
        loc[i] = sum; sum += v;
    }
    sh[t] = sum; __syncthreads();
    for (int s = 1; s < 1024; s <<= 1) {
        int v = (t >= s) ? sh[t - s] : 0;
        __syncthreads();
        sh[t] += v;
        __syncthreads();
    }
    int base = (t > 0) ? sh[t - 1] : 0;
    #pragma unroll
    for (int i = 0; i < IPT; i++) {
        int idx = t * IPT + i;
        if (idx < NPAIR) g_off[idx] = base + loc[i];
    }
    if (t == 0) g_off[NPAIR] = sh[1023];
}

__global__ void scatter_k(const int* __restrict__ idnb_i, const int* __restrict__ idnb_j,
                          const int* __restrict__ Z, int E) {
    int e = blockIdx.x * 256 + threadIdx.x;
    if (e < E) {
        int pr = Z[idnb_i[e]] * NSP + Z[idnb_j[e]];
        int pos = g_off[pr] + atomicAdd(&g_cur[pr], 1);
        g_perm[pos] = e;
    }
}

// ---------------- main edge kernel (R7 structure, pair-sorted order) ----------------
__global__ __launch_bounds__(256, 4)
void edge_kernel(const float* __restrict__ rbf,
                 const int* __restrict__ idnb_i,
                 const int* __restrict__ idnb_j,
                 const float* __restrict__ R,
                 const int* __restrict__ Z,
                 float* __restrict__ out,
                 int E) {
    __shared__ float s_Wc[NRBF * EMB];
    __shared__ float s_C[3 * EMB];
    __shared__ float s_S1[NSP * 3];
    __shared__ float s_S2[NSP * 3];
    __shared__ float s_sb;

    for (int i = threadIdx.x; i < NRBF * EMB; i += 256) s_Wc[i] = g_Wc[i];
    for (int i = threadIdx.x; i < 3 * EMB; i += 256)    s_C[i] = g_C[i];
    for (int i = threadIdx.x; i < NSP * 3; i += 256) { s_S1[i] = g_S1[i]; s_S2[i] = g_S2[i]; }
    if (threadIdx.x == 0) s_sb = g_sb;
    __syncthreads();

    const int lane  = threadIdx.x & 31;
    const int warp  = blockIdx.x * (blockDim.x >> 5) + (threadIdx.x >> 5);
    const int nwarp = gridDim.x * (blockDim.x >> 5);
    const int ntiles = (E + EPW - 1) / EPW;
    const size_t o2 = (size_t)E * EMB;

    const float4* __restrict__ Tcf = reinterpret_cast<const float4*>(g_Tc);
    const uint2*  __restrict__ Vch = reinterpret_cast<const uint2*>(g_Vc);
    const float4* __restrict__ Wcf = reinterpret_cast<const float4*>(s_Wc);
    const float4* __restrict__ Cf  = reinterpret_cast<const float4*>(s_C);

    for (int t = warp; t < ntiles; t += nwarp) {
        int base = t * EPW;
        float4 acc[EPW];
        float bdx[EPW], bdy[EPW], bdz[EPW];
        int pr[EPW], eidx[EPW];
        float rv[EPW];

        #pragma unroll
        for (int e = 0; e < EPW; e++) {
            int idx = base + e;
            if (idx >= E) idx = E - 1;
            int edge = g_perm[idx];
            eidx[e] = edge;
            int i = idnb_i[edge];
            int j = idnb_j[edge];
            int zi = Z[i], zj = Z[j];
            pr[e] = zi * NSP + zj;
            float bx = R[j * 3 + 0] - R[i * 3 + 0];
            float by = R[j * 3 + 1] - R[i * 3 + 1];
            float bz = R[j * 3 + 2] - R[i * 3 + 2];
            float n = sqrtf(bx * bx + by * by + bz * bz) + 1e-8f;
            float inv = 1.0f / n;
            bdx[e] = bx * inv; bdy[e] = by * inv; bdz[e] = bz * inv;
            rv[e] = rbf[edge * NRBF + (lane & 15)];

            float sx = bdx[e] * (s_S1[zi * 3 + 0] + s_S2[zj * 3 + 0])
                     + bdy[e] * (s_S1[zi * 3 + 1] + s_S2[zj * 3 + 1])
                     + bdz[e] * (s_S1[zi * 3 + 2] + s_S2[zj * 3 + 2])
                     + s_sb;
            if (lane < 3) {
                float comp = (lane == 0) ? bdx[e] : (lane == 1) ? bdy[e] : bdz[e];
                out[o2 + (size_t)edge * 3 + lane] = comp * sx;
            }
        }

        #pragma unroll
        for (int e = 0; e < EPW; e++)
            acc[e] = Tcf[pr[e] * 32 + lane];

        #pragma unroll
        for (int r = 0; r < NRBF; r++) {
            float4 w = Wcf[r * 32 + lane];
            #pragma unroll
            for (int e = 0; e < EPW; e++) {
                float c = __shfl_sync(0xffffffffu, rv[e], r);
                acc[e].x = fmaf(c, w.x, acc[e].x);
                acc[e].y = fmaf(c, w.y, acc[e].y);
                acc[e].z = fmaf(c, w.z, acc[e].z);
                acc[e].w = fmaf(c, w.w, acc[e].w);
            }
        }

        {
            float4 c0 = Cf[lane], c1 = Cf[32 + lane], c2 = Cf[64 + lane];
            #pragma unroll
            for (int e = 0; e < EPW; e++) {
                acc[e].x += bdx[e] * c0.x + bdy[e] * c1.x + bdz[e] * c2.x;
                acc[e].y += bdx[e] * c0.y + bdy[e] * c1.y + bdz[e] * c2.y;
                acc[e].z += bdx[e] * c0.z + bdy[e] * c1.z + bdz[e] * c2.z;
                acc[e].w += bdx[e] * c0.w + bdy[e] * c1.w + bdz[e] * c2.w;
            }
        }

        const int PD[6]  = {0, 1, 2, 0, 0, 1};
        const int PDP[6] = {0, 1, 2, 1, 2, 2};
        #pragma unroll
        for (int p = 0; p < 6; p++) {
            const int d = PD[p], dp = PDP[p];
            #pragma unroll
            for (int e = 0; e < EPW; e++) {
                float b1 = (d  == 0) ? bdx[e] : (d  == 1) ? bdy[e] : bdz[e];
                float b2 = (dp == 0) ? bdx[e] : (dp == 1) ? bdy[e] : bdz[e];
                float c = b1 * b2;
                uint2 r1 = Vch[(pr[e] * 6 + p) * 32 + lane];
                float2 a0 = __half22float2(*reinterpret_cast<__half2*>(&r1.x));
                float2 a1 = __half22float2(*reinterpret_cast<__half2*>(&r1.y));
                acc[e].x = fmaf(c, a0.x, acc[e].x);
                acc[e].y = fmaf(c, a0.y, acc[e].y);
                acc[e].z = fmaf(c, a1.x, acc[e].z);
                acc[e].w = fmaf(c, a1.y, acc[e].w);
            }
        }

        #pragma unroll
        for (int e = 0; e < EPW; e++)
            reinterpret_cast<float4*>(out + (size_t)eidx[e] * EMB)[lane] = acc[e];
    }
}

// ---------------- launcher ----------------
extern "C" void kernel_launch(void* const* d_in, const int* in_sizes, int n_in,
                              void* d_out, int out_size) {
    const int*   Z        = (const int*)d_in[0];
    const float* rbf      = (const float*)d_in[1];
    const int*   idnb_i   = (const int*)d_in[2];
    const int*   idnb_j   = (const int*)d_in[3];
    const float* R        = (const float*)d_in[4];
    const float* emb      = (const float*)d_in[5];
    const float* vemb     = (const float*)d_in[6];
    const float* W_rbf    = (const float*)d_in[7];
    const float* b_rbf    = (const float*)d_in[8];
    const float* W_scalar = (const float*)d_in[9];
    const float* b_scalar = (const float*)d_in[10];
    const float* W_vector = (const float*)d_in[11];
    const float* b_vector = (const float*)d_in[12];
    const float* W_v2s    = (const float*)d_in[13];
    int E = in_sizes[2];
    if (E > EMAX) E = EMAX;

    int eb = (E + 255) / 256;
    zero_k<<<(NPAIR + 255) / 256, 256>>>();
    pre_tables<<<NRBF + 1 + NSP + 3, 128>>>(W_rbf, b_rbf, W_scalar, b_scalar, emb,
                                            b_vector, W_v2s);
    pre_UVS<<<NSP, 128>>>(vemb, W_vector, W_v2s);
    hist_k<<<eb, 256>>>(idnb_i, idnb_j, Z, E);
    scan_k<<<1, 1024>>>();
    scatter_k<<<eb, 256>>>(idnb_i, idnb_j, Z, E);
    pre_pair<<<NPAIR, 128>>>();
    edge_kernel<<<2048, 256>>>(rbf, idnb_i, idnb_j, R, Z, (float*)d_out, E);
}